// round 1
// baseline (speedup 1.0000x reference)
#include <cuda_runtime.h>

// Problem dims
#define B_SZ 4
#define T_SZ 256
#define U_SZ 64
#define E_DIM 512
#define P_DIM 640
#define H_DIM 512
#define V_DIM 1024

// Scratch for stage-1 projections (device globals: no allocation allowed)
__device__ float g_enc[B_SZ * T_SZ * H_DIM];   // (1024, 512)
__device__ float g_pred[B_SZ * U_SZ * H_DIM];  // (256, 512)

// ---------------------------------------------------------------------------
// Stage 1: out[M, 512] = X[M, K] @ W[K, 512] + bias
// BM=64, BN=64, BK=16, 256 threads, 4x4 microtile.
// which == 0 -> g_enc, which == 1 -> g_pred
// ---------------------------------------------------------------------------
__global__ __launch_bounds__(256) void proj_kernel(
    const float* __restrict__ X, const float* __restrict__ W,
    const float* __restrict__ bias, int M, int K, int which)
{
    float* out = which ? g_pred : g_enc;

    __shared__ float Xs[16][68];   // [k][m], padded (68*4 = 272 = 17*16, float4-safe)
    __shared__ float Ws[16][64];   // [k][n]

    const int tid = threadIdx.x;
    const int m0 = blockIdx.y * 64;
    const int n0 = blockIdx.x * 64;

    // A-tile load mapping: 64 rows x 4 float4 chunks = 256 slots
    const int lm  = tid >> 2;          // 0..63
    const int lkc = (tid & 3) << 2;    // 0,4,8,12
    // B-tile load mapping: 16 rows x 16 float4 chunks
    const int wkr = tid >> 4;          // 0..15
    const int wc  = (tid & 15) << 2;   // 0..60

    const int rowb = (tid >> 4) << 2;  // 0..60
    const int colb = (tid & 15) << 2;  // 0..60

    float acc[4][4];
    #pragma unroll
    for (int i = 0; i < 4; i++)
        #pragma unroll
        for (int j = 0; j < 4; j++) acc[i][j] = 0.0f;

    for (int k0 = 0; k0 < K; k0 += 16) {
        float4 xv = *reinterpret_cast<const float4*>(X + (size_t)(m0 + lm) * K + k0 + lkc);
        Xs[lkc + 0][lm] = xv.x;
        Xs[lkc + 1][lm] = xv.y;
        Xs[lkc + 2][lm] = xv.z;
        Xs[lkc + 3][lm] = xv.w;
        *reinterpret_cast<float4*>(&Ws[wkr][wc]) =
            *reinterpret_cast<const float4*>(W + (size_t)(k0 + wkr) * H_DIM + n0 + wc);
        __syncthreads();

        #pragma unroll
        for (int kk = 0; kk < 16; kk++) {
            float a[4], bb[4];
            *reinterpret_cast<float4*>(a)  = *reinterpret_cast<float4*>(&Xs[kk][rowb]);
            *reinterpret_cast<float4*>(bb) = *reinterpret_cast<float4*>(&Ws[kk][colb]);
            #pragma unroll
            for (int i = 0; i < 4; i++)
                #pragma unroll
                for (int j = 0; j < 4; j++)
                    acc[i][j] = fmaf(a[i], bb[j], acc[i][j]);
        }
        __syncthreads();
    }

    float bb[4];
    *reinterpret_cast<float4*>(bb) = *reinterpret_cast<const float4*>(bias + n0 + colb);
    #pragma unroll
    for (int i = 0; i < 4; i++) {
        float4 v;
        v.x = acc[i][0] + bb[0];
        v.y = acc[i][1] + bb[1];
        v.z = acc[i][2] + bb[2];
        v.w = acc[i][3] + bb[3];
        *reinterpret_cast<float4*>(out + (size_t)(m0 + rowb + i) * H_DIM + n0 + colb) = v;
    }
}

// ---------------------------------------------------------------------------
// Stage 2: out[bt, u, v] = relu(enc[bt, :] + pred[b, u, :]) @ W_out + b_out
// Block handles 2 consecutive (b,t) rows x all 64 u = 128 M-rows, 128 v-cols.
// BM=128, BN=128, BK=16, 256 threads, 8x8 microtile.
// ---------------------------------------------------------------------------
__global__ __launch_bounds__(256) void joint_kernel(
    const float* __restrict__ Wout, const float* __restrict__ bout,
    float* __restrict__ out)
{
    __shared__ float As[16][132];   // [k][r], padded (132*4 = 528 = 33*16, float4-safe)
    __shared__ float Bs[16][128];   // [k][v]

    const int tid = threadIdx.x;
    const int n0  = blockIdx.x * 128;
    const int bt0 = blockIdx.y * 2;          // two consecutive (b,t); never crosses b (T even)
    const int b   = bt0 >> 8;                // bt / 256

    const float* encp  = g_enc  + (size_t)bt0 * H_DIM;          // 2 rows
    const float* predp = g_pred + (size_t)b * U_SZ * H_DIM;     // 64 rows

    const int rowb = (tid >> 4) << 3;   // 0..120
    const int colb = (tid & 15) << 3;   // 0..120

    float acc[8][8];
    #pragma unroll
    for (int i = 0; i < 8; i++)
        #pragma unroll
        for (int j = 0; j < 8; j++) acc[i][j] = 0.0f;

    for (int k0 = 0; k0 < H_DIM; k0 += 16) {
        // A tile: 128 rows x 16 k = 512 float4 slots; 2 per thread.
        #pragma unroll
        for (int s = 0; s < 2; s++) {
            int idx = tid + s * 256;
            int r   = idx >> 2;            // 0..127
            int kc  = (idx & 3) << 2;      // 0,4,8,12
            int u   = r & 63;
            int tl  = r >> 6;              // 0 or 1
            float4 pv = *reinterpret_cast<const float4*>(predp + (size_t)u * H_DIM + k0 + kc);
            float4 ev = *reinterpret_cast<const float4*>(encp + (size_t)tl * H_DIM + k0 + kc);
            As[kc + 0][r] = fmaxf(pv.x + ev.x, 0.0f);
            As[kc + 1][r] = fmaxf(pv.y + ev.y, 0.0f);
            As[kc + 2][r] = fmaxf(pv.z + ev.z, 0.0f);
            As[kc + 3][r] = fmaxf(pv.w + ev.w, 0.0f);

            // B tile: 16 rows x 128 cols = 512 float4 slots; 2 per thread.
            int kr = idx >> 5;             // 0..15
            int c  = (idx & 31) << 2;      // 0..124
            *reinterpret_cast<float4*>(&Bs[kr][c]) =
                *reinterpret_cast<const float4*>(Wout + (size_t)(k0 + kr) * V_DIM + n0 + c);
        }
        __syncthreads();

        #pragma unroll
        for (int kk = 0; kk < 16; kk++) {
            float a[8], bb[8];
            *reinterpret_cast<float4*>(a)      = *reinterpret_cast<float4*>(&As[kk][rowb]);
            *reinterpret_cast<float4*>(a + 4)  = *reinterpret_cast<float4*>(&As[kk][rowb + 4]);
            *reinterpret_cast<float4*>(bb)     = *reinterpret_cast<float4*>(&Bs[kk][colb]);
            *reinterpret_cast<float4*>(bb + 4) = *reinterpret_cast<float4*>(&Bs[kk][colb + 4]);
            #pragma unroll
            for (int i = 0; i < 8; i++)
                #pragma unroll
                for (int j = 0; j < 8; j++)
                    acc[i][j] = fmaf(a[i], bb[j], acc[i][j]);
        }
        __syncthreads();
    }

    // Epilogue: add bias, write out (B,T,U,V) contiguous.
    float bb[8];
    *reinterpret_cast<float4*>(bb)     = *reinterpret_cast<const float4*>(bout + n0 + colb);
    *reinterpret_cast<float4*>(bb + 4) = *reinterpret_cast<const float4*>(bout + n0 + colb + 4);
    #pragma unroll
    for (int i = 0; i < 8; i++) {
        int r  = rowb + i;
        int bt = bt0 + (r >> 6);
        int u  = r & 63;
        float* op = out + ((size_t)(bt * U_SZ + u)) * V_DIM + n0 + colb;
        float4 v0, v1;
        v0.x = acc[i][0] + bb[0];
        v0.y = acc[i][1] + bb[1];
        v0.z = acc[i][2] + bb[2];
        v0.w = acc[i][3] + bb[3];
        v1.x = acc[i][4] + bb[4];
        v1.y = acc[i][5] + bb[5];
        v1.z = acc[i][6] + bb[6];
        v1.w = acc[i][7] + bb[7];
        *reinterpret_cast<float4*>(op)     = v0;
        *reinterpret_cast<float4*>(op + 4) = v1;
    }
}

// ---------------------------------------------------------------------------
// kernel_launch
// Inputs (metadata order):
//  0: encoder_output (4,256,512) f32      1: prediction_output (4,64,640) f32
//  2: W_enc (512,512)                     3: b_enc (512,)
//  4: W_pred (640,512)                    5: b_pred (512,)
//  6: W_out (512,1024)                    7: b_out (1024,)
// Output: (4,256,64,1024) f32
// ---------------------------------------------------------------------------
extern "C" void kernel_launch(void* const* d_in, const int* in_sizes, int n_in,
                              void* d_out, int out_size)
{
    const float* enc_in  = (const float*)d_in[0];
    const float* pred_in = (const float*)d_in[1];
    const float* W_enc   = (const float*)d_in[2];
    const float* b_enc   = (const float*)d_in[3];
    const float* W_pred  = (const float*)d_in[4];
    const float* b_pred  = (const float*)d_in[5];
    const float* W_out   = (const float*)d_in[6];
    const float* b_out   = (const float*)d_in[7];
    float* out = (float*)d_out;

    // Stage 1: projections into device scratch
    proj_kernel<<<dim3(H_DIM / 64, (B_SZ * T_SZ) / 64), 256>>>(
        enc_in, W_enc, b_enc, B_SZ * T_SZ, E_DIM, /*which=*/0);
    proj_kernel<<<dim3(H_DIM / 64, (B_SZ * U_SZ) / 64), 256>>>(
        pred_in, W_pred, b_pred, B_SZ * U_SZ, P_DIM, /*which=*/1);

    // Stage 2: fused relu(enc+pred) @ W_out + b_out
    joint_kernel<<<dim3(V_DIM / 128, (B_SZ * T_SZ) / 2), 256>>>(W_out, b_out, out);
}

// round 5
// speedup vs baseline: 1.6940x; 1.6940x over previous
#include <cuda_runtime.h>
#include <cuda_bf16.h>
#include <cstdint>

// Problem dims
#define B_SZ 4
#define T_SZ 256
#define U_SZ 64
#define E_DIM 512
#define P_DIM 640
#define H_DIM 512
#define V_DIM 1024

// Device scratch (no allocation allowed)
__device__ float g_enc[B_SZ * T_SZ * H_DIM];             // (1024, 512) fp32
__device__ float g_pred[B_SZ * U_SZ * H_DIM];            // (256, 512) fp32
__device__ __nv_bfloat16 g_Whi[V_DIM * H_DIM];           // W_out^T hi  [n][k]
__device__ __nv_bfloat16 g_Wlo[V_DIM * H_DIM];           // W_out^T lo  [n][k]

__device__ __forceinline__ uint32_t smem_u32(const void* p) {
    uint32_t a;
    asm("{ .reg .u64 t; cvta.to.shared.u64 t, %1; cvt.u32.u64 %0, t; }" : "=r"(a) : "l"(p));
    return a;
}

__device__ __forceinline__ void ldmx4(uint32_t* r, uint32_t addr) {
    asm volatile("ldmatrix.sync.aligned.m8n8.x4.shared.b16 {%0,%1,%2,%3}, [%4];"
        : "=r"(r[0]), "=r"(r[1]), "=r"(r[2]), "=r"(r[3]) : "r"(addr));
}
__device__ __forceinline__ void ldmx2(uint32_t* r, uint32_t addr) {
    asm volatile("ldmatrix.sync.aligned.m8n8.x2.shared.b16 {%0,%1}, [%2];"
        : "=r"(r[0]), "=r"(r[1]) : "r"(addr));
}
__device__ __forceinline__ void mma16816(float* c, const uint32_t* a, const uint32_t* b) {
    asm volatile("mma.sync.aligned.m16n8k16.row.col.f32.bf16.bf16.f32 "
        "{%0,%1,%2,%3}, {%4,%5,%6,%7}, {%8,%9}, {%0,%1,%2,%3};"
        : "+f"(c[0]), "+f"(c[1]), "+f"(c[2]), "+f"(c[3])
        : "r"(a[0]), "r"(a[1]), "r"(a[2]), "r"(a[3]), "r"(b[0]), "r"(b[1]));
}

// ---------------------------------------------------------------------------
// Stage 1: out[M, 512] = X[M, K] @ W[K, 512] + bias  (SIMT, fp32)
// ---------------------------------------------------------------------------
__global__ __launch_bounds__(256) void proj_kernel(
    const float* __restrict__ X, const float* __restrict__ W,
    const float* __restrict__ bias, int M, int K, int which)
{
    float* out = which ? g_pred : g_enc;

    __shared__ float Xs[16][68];
    __shared__ float Ws[16][64];

    const int tid = threadIdx.x;
    const int m0 = blockIdx.y * 64;
    const int n0 = blockIdx.x * 64;

    const int lm  = tid >> 2;
    const int lkc = (tid & 3) << 2;
    const int wkr = tid >> 4;
    const int wc  = (tid & 15) << 2;
    const int rowb = (tid >> 4) << 2;
    const int colb = (tid & 15) << 2;

    float acc[4][4];
    #pragma unroll
    for (int i = 0; i < 4; i++)
        #pragma unroll
        for (int j = 0; j < 4; j++) acc[i][j] = 0.0f;

    for (int k0 = 0; k0 < K; k0 += 16) {
        float4 xv = *reinterpret_cast<const float4*>(X + (size_t)(m0 + lm) * K + k0 + lkc);
        Xs[lkc + 0][lm] = xv.x;
        Xs[lkc + 1][lm] = xv.y;
        Xs[lkc + 2][lm] = xv.z;
        Xs[lkc + 3][lm] = xv.w;
        *reinterpret_cast<float4*>(&Ws[wkr][wc]) =
            *reinterpret_cast<const float4*>(W + (size_t)(k0 + wkr) * H_DIM + n0 + wc);
        __syncthreads();

        #pragma unroll
        for (int kk = 0; kk < 16; kk++) {
            float a[4], bb[4];
            *reinterpret_cast<float4*>(a)  = *reinterpret_cast<float4*>(&Xs[kk][rowb]);
            *reinterpret_cast<float4*>(bb) = *reinterpret_cast<float4*>(&Ws[kk][colb]);
            #pragma unroll
            for (int i = 0; i < 4; i++)
                #pragma unroll
                for (int j = 0; j < 4; j++)
                    acc[i][j] = fmaf(a[i], bb[j], acc[i][j]);
        }
        __syncthreads();
    }

    float bb[4];
    *reinterpret_cast<float4*>(bb) = *reinterpret_cast<const float4*>(bias + n0 + colb);
    #pragma unroll
    for (int i = 0; i < 4; i++) {
        float4 v;
        v.x = acc[i][0] + bb[0];
        v.y = acc[i][1] + bb[1];
        v.z = acc[i][2] + bb[2];
        v.w = acc[i][3] + bb[3];
        *reinterpret_cast<float4*>(out + (size_t)(m0 + rowb + i) * H_DIM + n0 + colb) = v;
    }
}

// ---------------------------------------------------------------------------
// Transpose + bf16-split W_out: g_Whi/g_Wlo[n][k] = split(W_out[k][n])
// ---------------------------------------------------------------------------
__global__ void split_w_kernel(const float* __restrict__ W)
{
    __shared__ float t[32][33];
    const int n0 = blockIdx.x * 32;
    const int k0 = blockIdx.y * 32;
    const int tx = threadIdx.x;   // 0..31
    const int ty = threadIdx.y;   // 0..7

    for (int j = ty; j < 32; j += 8)
        t[j][tx] = W[(size_t)(k0 + j) * V_DIM + n0 + tx];
    __syncthreads();
    for (int j = ty; j < 32; j += 8) {
        float v = t[tx][j];   // = W[k0+tx][n0+j]
        __nv_bfloat16 hi = __float2bfloat16_rn(v);
        __nv_bfloat16 lo = __float2bfloat16_rn(v - __bfloat162float(hi));
        g_Whi[(size_t)(n0 + j) * H_DIM + k0 + tx] = hi;
        g_Wlo[(size_t)(n0 + j) * H_DIM + k0 + tx] = lo;
    }
}

// ---------------------------------------------------------------------------
// Stage 2 (mma.sync bf16 3-pass split):
//   out[bt,u,:] = relu(enc[bt]+pred[b,u]) @ W_out + b_out
// CTA: M=64 (one bt, all 64 u) x N=128, BK=32. 8 warps, warp tile 32x32.
// SMEM tiles padded to stride 40 bf16 (80 B) -> conflict-free ldmatrix.
// ---------------------------------------------------------------------------
#define AS_STRIDE 40
#define CHUNK_K 32

__global__ __launch_bounds__(256, 2) void joint_mma_kernel(
    const float* __restrict__ bout, float* __restrict__ out)
{
    __shared__ __nv_bfloat16 As_hi[64 * AS_STRIDE];
    __shared__ __nv_bfloat16 As_lo[64 * AS_STRIDE];
    __shared__ __nv_bfloat16 Bs_hi[128 * AS_STRIDE];
    __shared__ __nv_bfloat16 Bs_lo[128 * AS_STRIDE];

    const int tid  = threadIdx.x;
    const int lane = tid & 31;
    const int wid  = tid >> 5;
    const int wm   = wid & 1;    // 0..1 -> m offset 0/32
    const int wn   = wid >> 1;   // 0..3 -> n offset 0/32/64/96

    const int n0 = blockIdx.x * 128;
    const int bt = blockIdx.y;           // 0..1023
    const int b  = bt >> 8;

    // ---- gmem prefetch mapping ----
    const int ar  = tid >> 2;            // 0..63 : A row (= u), also B row pair base
    const int kc  = (tid & 3) << 3;      // 0,8,16,24 : k offset within chunk

    const float* encp  = g_enc  + (size_t)bt * H_DIM + kc;
    const float* predp = g_pred + ((size_t)b * U_SZ + ar) * H_DIM + kc;
    const __nv_bfloat16* whi = g_Whi + (size_t)(n0 + ar) * H_DIM + kc;
    const __nv_bfloat16* wlo = g_Wlo + (size_t)(n0 + ar) * H_DIM + kc;

    // ---- ldmatrix lane addressing ----
    const int arow  = (lane & 7) + (((lane >> 3) & 1) << 3);   // 0..15
    const int akoff = (lane >> 4) << 3;                        // 0 or 8
    const int brow  = lane & 7;
    const int bkoff = ((lane >> 3) & 1) << 3;

    const uint32_t as_hi_b = smem_u32(As_hi);
    const uint32_t as_lo_b = smem_u32(As_lo);
    const uint32_t bs_hi_b = smem_u32(Bs_hi);
    const uint32_t bs_lo_b = smem_u32(Bs_lo);

    uint32_t aH[2], aL[2];               // per mt base addresses (ks adds 32 B)
    #pragma unroll
    for (int mt = 0; mt < 2; mt++) {
        uint32_t off = (uint32_t)(((wm * 32 + mt * 16 + arow) * AS_STRIDE + akoff) * 2);
        aH[mt] = as_hi_b + off;
        aL[mt] = as_lo_b + off;
    }
    uint32_t bH[4], bL[4];
    #pragma unroll
    for (int nt = 0; nt < 4; nt++) {
        uint32_t off = (uint32_t)(((wn * 32 + nt * 8 + brow) * AS_STRIDE + bkoff) * 2);
        bH[nt] = bs_hi_b + off;
        bL[nt] = bs_lo_b + off;
    }

    float acc[2][4][4];
    #pragma unroll
    for (int mt = 0; mt < 2; mt++)
        #pragma unroll
        for (int nt = 0; nt < 4; nt++)
            #pragma unroll
            for (int i = 0; i < 4; i++) acc[mt][nt][i] = 0.0f;

    // prefetch registers
    float4 pe0, pe1, pp0, pp1;
    uint4 vbh0, vbh1, vbl0, vbl1;

    // chunk 0 prefetch
    pe0 = *reinterpret_cast<const float4*>(encp);
    pe1 = *reinterpret_cast<const float4*>(encp + 4);
    pp0 = *reinterpret_cast<const float4*>(predp);
    pp1 = *reinterpret_cast<const float4*>(predp + 4);
    vbh0 = *reinterpret_cast<const uint4*>(whi);
    vbh1 = *reinterpret_cast<const uint4*>(whi + (size_t)64 * H_DIM);
    vbl0 = *reinterpret_cast<const uint4*>(wlo);
    vbl1 = *reinterpret_cast<const uint4*>(wlo + (size_t)64 * H_DIM);

    const int a_off = ar * AS_STRIDE + kc;

    #pragma unroll 1
    for (int ch = 0; ch < H_DIM / CHUNK_K; ch++) {
        // ---- store A (relu + bf16 split) ----
        {
            float v[8];
            v[0] = pe0.x + pp0.x; v[1] = pe0.y + pp0.y;
            v[2] = pe0.z + pp0.z; v[3] = pe0.w + pp0.w;
            v[4] = pe1.x + pp1.x; v[5] = pe1.y + pp1.y;
            v[6] = pe1.z + pp1.z; v[7] = pe1.w + pp1.w;
            unsigned short hs[8], ls[8];
            #pragma unroll
            for (int i = 0; i < 8; i++) {
                float r = fmaxf(v[i], 0.0f);
                __nv_bfloat16 h = __float2bfloat16_rn(r);
                float hf = __bfloat162float(h);
                __nv_bfloat16 l = __float2bfloat16_rn(r - hf);
                hs[i] = *reinterpret_cast<unsigned short*>(&h);
                ls[i] = *reinterpret_cast<unsigned short*>(&l);
            }
            *reinterpret_cast<uint4*>(&As_hi[a_off]) = *reinterpret_cast<uint4*>(hs);
            *reinterpret_cast<uint4*>(&As_lo[a_off]) = *reinterpret_cast<uint4*>(ls);
        }
        // ---- store B ----
        *reinterpret_cast<uint4*>(&Bs_hi[a_off])                     = vbh0;
        *reinterpret_cast<uint4*>(&Bs_hi[a_off + 64 * AS_STRIDE])    = vbh1;
        *reinterpret_cast<uint4*>(&Bs_lo[a_off])                     = vbl0;
        *reinterpret_cast<uint4*>(&Bs_lo[a_off + 64 * AS_STRIDE])    = vbl1;
        __syncthreads();

        // ---- prefetch next chunk (overlaps with MMA below) ----
        if (ch < H_DIM / CHUNK_K - 1) {
            int k0 = (ch + 1) * CHUNK_K;
            pe0 = *reinterpret_cast<const float4*>(encp + k0);
            pe1 = *reinterpret_cast<const float4*>(encp + k0 + 4);
            pp0 = *reinterpret_cast<const float4*>(predp + k0);
            pp1 = *reinterpret_cast<const float4*>(predp + k0 + 4);
            vbh0 = *reinterpret_cast<const uint4*>(whi + k0);
            vbh1 = *reinterpret_cast<const uint4*>(whi + (size_t)64 * H_DIM + k0);
            vbl0 = *reinterpret_cast<const uint4*>(wlo + k0);
            vbl1 = *reinterpret_cast<const uint4*>(wlo + (size_t)64 * H_DIM + k0);
        }

        // ---- MMA: 2 k16 steps x (2 mt x 4 nt x 3 passes) ----
        #pragma unroll
        for (int ks = 0; ks < 2; ks++) {
            const uint32_t kadd = ks * 32;   // 16 bf16 = 32 bytes
            uint32_t afh[2][4], afl[2][4];
            #pragma unroll
            for (int mt = 0; mt < 2; mt++) {
                ldmx4(afh[mt], aH[mt] + kadd);
                ldmx4(afl[mt], aL[mt] + kadd);
            }
            uint32_t bfh[4][2], bfl[4][2];
            #pragma unroll
            for (int nt = 0; nt < 4; nt++) {
                ldmx2(bfh[nt], bH[nt] + kadd);
                ldmx2(bfl[nt], bL[nt] + kadd);
            }
            #pragma unroll
            for (int mt = 0; mt < 2; mt++)
                #pragma unroll
                for (int nt = 0; nt < 4; nt++) {
                    mma16816(acc[mt][nt], afh[mt], bfh[nt]);
                    mma16816(acc[mt][nt], afh[mt], bfl[nt]);
                    mma16816(acc[mt][nt], afl[mt], bfh[nt]);
                }
        }
        __syncthreads();
    }

    // ---- epilogue: bias + store ----
    #pragma unroll
    for (int mt = 0; mt < 2; mt++) {
        const int m = wm * 32 + mt * 16 + (lane >> 2);     // u row
        float* orow = out + ((size_t)bt * U_SZ + m) * V_DIM;
        #pragma unroll
        for (int nt = 0; nt < 4; nt++) {
            const int ncol = n0 + wn * 32 + nt * 8 + ((lane & 3) << 1);
            float2 bv = *reinterpret_cast<const float2*>(bout + ncol);
            float2 o0, o1;
            o0.x = acc[mt][nt][0] + bv.x;
            o0.y = acc[mt][nt][1] + bv.y;
            o1.x = acc[mt][nt][2] + bv.x;
            o1.y = acc[mt][nt][3] + bv.y;
            *reinterpret_cast<float2*>(orow + ncol) = o0;
            *reinterpret_cast<float2*>(orow + (size_t)8 * V_DIM + ncol) = o1;
        }
    }
}

// ---------------------------------------------------------------------------
// kernel_launch
// Inputs: 0 enc(4,256,512) 1 pred(4,64,640) 2 W_enc(512,512) 3 b_enc(512)
//         4 W_pred(640,512) 5 b_pred(512) 6 W_out(512,1024) 7 b_out(1024)
// Output: (4,256,64,1024) f32
// ---------------------------------------------------------------------------
extern "C" void kernel_launch(void* const* d_in, const int* in_sizes, int n_in,
                              void* d_out, int out_size)
{
    const float* enc_in  = (const float*)d_in[0];
    const float* pred_in = (const float*)d_in[1];
    const float* W_enc   = (const float*)d_in[2];
    const float* b_enc   = (const float*)d_in[3];
    const float* W_pred  = (const float*)d_in[4];
    const float* b_pred  = (const float*)d_in[5];
    const float* W_out   = (const float*)d_in[6];
    const float* b_out   = (const float*)d_in[7];
    float* out = (float*)d_out;

    // Stage 1: projections into device scratch (fp32)
    proj_kernel<<<dim3(H_DIM / 64, (B_SZ * T_SZ) / 64), 256>>>(
        enc_in, W_enc, b_enc, B_SZ * T_SZ, E_DIM, /*which=*/0);
    proj_kernel<<<dim3(H_DIM / 64, (B_SZ * U_SZ) / 64), 256>>>(
        pred_in, W_pred, b_pred, B_SZ * U_SZ, P_DIM, /*which=*/1);

    // W_out transpose + bf16 split
    split_w_kernel<<<dim3(V_DIM / 32, H_DIM / 32), dim3(32, 8)>>>(W_out);

    // Stage 2: mma.sync joint GEMM
    joint_mma_kernel<<<dim3(V_DIM / 128, B_SZ * T_SZ), 256>>>(b_out, out);
}

// round 7
// speedup vs baseline: 2.0759x; 1.2255x over previous
#include <cuda_runtime.h>
#include <cuda_bf16.h>
#include <cstdint>

// Problem dims
#define B_SZ 4
#define T_SZ 256
#define U_SZ 64
#define E_DIM 512
#define P_DIM 640
#define H_DIM 512
#define V_DIM 1024

// Device scratch (no allocation allowed)
__device__ float g_enc[B_SZ * T_SZ * H_DIM];             // (1024, 512) fp32
__device__ float g_pred[B_SZ * U_SZ * H_DIM];            // (256, 512) fp32
__device__ __nv_bfloat16 g_Whi[V_DIM * H_DIM];           // W_out^T hi  [n][k]
__device__ __nv_bfloat16 g_Wlo[V_DIM * H_DIM];           // W_out^T lo  [n][k]

__device__ __forceinline__ uint32_t smem_u32(const void* p) {
    uint32_t a;
    asm("{ .reg .u64 t; cvta.to.shared.u64 t, %1; cvt.u32.u64 %0, t; }" : "=r"(a) : "l"(p));
    return a;
}
__device__ __forceinline__ void ldmx4(uint32_t* r, uint32_t addr) {
    asm volatile("ldmatrix.sync.aligned.m8n8.x4.shared.b16 {%0,%1,%2,%3}, [%4];"
        : "=r"(r[0]), "=r"(r[1]), "=r"(r[2]), "=r"(r[3]) : "r"(addr));
}
__device__ __forceinline__ void ldmx2(uint32_t* r, uint32_t addr) {
    asm volatile("ldmatrix.sync.aligned.m8n8.x2.shared.b16 {%0,%1}, [%2];"
        : "=r"(r[0]), "=r"(r[1]) : "r"(addr));
}
__device__ __forceinline__ void mma16816(float* c, const uint32_t* a, const uint32_t* b) {
    asm volatile("mma.sync.aligned.m16n8k16.row.col.f32.bf16.bf16.f32 "
        "{%0,%1,%2,%3}, {%4,%5,%6,%7}, {%8,%9}, {%0,%1,%2,%3};"
        : "+f"(c[0]), "+f"(c[1]), "+f"(c[2]), "+f"(c[3])
        : "r"(a[0]), "r"(a[1]), "r"(a[2]), "r"(a[3]), "r"(b[0]), "r"(b[1]));
}
__device__ __forceinline__ void cp16(uint32_t dst, const void* src) {
    asm volatile("{ .reg .u64 ga; cvta.to.global.u64 ga, %1; "
                 "cp.async.ca.shared.global [%0], [ga], 16; }"
        :: "r"(dst), "l"(src) : "memory");
}
#define CP_COMMIT() asm volatile("cp.async.commit_group;" ::: "memory")
#define CP_WAIT0()  asm volatile("cp.async.wait_group 0;" ::: "memory")

// ---------------------------------------------------------------------------
// Stage 1: out[M, 512] = X[M, K] @ W[K, 512] + bias  (SIMT, fp32)
// ---------------------------------------------------------------------------
__global__ __launch_bounds__(256) void proj_kernel(
    const float* __restrict__ X, const float* __restrict__ W,
    const float* __restrict__ bias, int M, int K, int which)
{
    float* out = which ? g_pred : g_enc;

    __shared__ float Xs[16][68];
    __shared__ float Ws[16][64];

    const int tid = threadIdx.x;
    const int m0 = blockIdx.y * 64;
    const int n0 = blockIdx.x * 64;

    const int lm  = tid >> 2;
    const int lkc = (tid & 3) << 2;
    const int wkr = tid >> 4;
    const int wc  = (tid & 15) << 2;
    const int rowb = (tid >> 4) << 2;
    const int colb = (tid & 15) << 2;

    float acc[4][4];
    #pragma unroll
    for (int i = 0; i < 4; i++)
        #pragma unroll
        for (int j = 0; j < 4; j++) acc[i][j] = 0.0f;

    for (int k0 = 0; k0 < K; k0 += 16) {
        float4 xv = *reinterpret_cast<const float4*>(X + (size_t)(m0 + lm) * K + k0 + lkc);
        Xs[lkc + 0][lm] = xv.x;
        Xs[lkc + 1][lm] = xv.y;
        Xs[lkc + 2][lm] = xv.z;
        Xs[lkc + 3][lm] = xv.w;
        *reinterpret_cast<float4*>(&Ws[wkr][wc]) =
            *reinterpret_cast<const float4*>(W + (size_t)(k0 + wkr) * H_DIM + n0 + wc);
        __syncthreads();

        #pragma unroll
        for (int kk = 0; kk < 16; kk++) {
            float a[4], bb[4];
            *reinterpret_cast<float4*>(a)  = *reinterpret_cast<float4*>(&Xs[kk][rowb]);
            *reinterpret_cast<float4*>(bb) = *reinterpret_cast<float4*>(&Ws[kk][colb]);
            #pragma unroll
            for (int i = 0; i < 4; i++)
                #pragma unroll
                for (int j = 0; j < 4; j++)
                    acc[i][j] = fmaf(a[i], bb[j], acc[i][j]);
        }
        __syncthreads();
    }

    float bb[4];
    *reinterpret_cast<float4*>(bb) = *reinterpret_cast<const float4*>(bias + n0 + colb);
    #pragma unroll
    for (int i = 0; i < 4; i++) {
        float4 v;
        v.x = acc[i][0] + bb[0];
        v.y = acc[i][1] + bb[1];
        v.z = acc[i][2] + bb[2];
        v.w = acc[i][3] + bb[3];
        *reinterpret_cast<float4*>(out + (size_t)(m0 + rowb + i) * H_DIM + n0 + colb) = v;
    }
}

// ---------------------------------------------------------------------------
// Transpose + bf16-split W_out: g_Whi/g_Wlo[n][k] = split(W_out[k][n])
// ---------------------------------------------------------------------------
__global__ void split_w_kernel(const float* __restrict__ W)
{
    __shared__ float t[32][33];
    const int n0 = blockIdx.x * 32;
    const int k0 = blockIdx.y * 32;
    const int tx = threadIdx.x;
    const int ty = threadIdx.y;

    for (int j = ty; j < 32; j += 8)
        t[j][tx] = W[(size_t)(k0 + j) * V_DIM + n0 + tx];
    __syncthreads();
    for (int j = ty; j < 32; j += 8) {
        float v = t[tx][j];
        __nv_bfloat16 hi = __float2bfloat16_rn(v);
        __nv_bfloat16 lo = __float2bfloat16_rn(v - __bfloat162float(hi));
        g_Whi[(size_t)(n0 + j) * H_DIM + k0 + tx] = hi;
        g_Wlo[(size_t)(n0 + j) * H_DIM + k0 + tx] = lo;
    }
}

// ---------------------------------------------------------------------------
// Stage 2: out = relu(enc+pred) @ W_out + b_out, bf16 3-pass split.
// CTA: M=128 (2 bt) x N=256. 16 warps, warp tile 32x64. BK=32.
// B (W hi/lo) via double-buffered cp.async; A built in regs -> SMEM.
// SMEM row stride 56 halves (112B): 16B-aligned + conflict-free ldmatrix.
// ---------------------------------------------------------------------------
#define STRH 56
#define ROWB 112
#define BK 32
#define A_ONE (128 * ROWB)            // 14336
#define B_ONE (256 * ROWB)            // 28672
#define OFF_AHI 0
#define OFF_ALO A_ONE
#define OFF_B0  (2 * A_ONE)
#define JSMEM (2 * A_ONE + 4 * B_ONE) // 143360

__global__ __launch_bounds__(512, 1) void joint_mma_kernel(
    const float* __restrict__ bout, float* __restrict__ out)
{
    extern __shared__ char smem[];
    const uint32_t sb = smem_u32(smem);

    const int tid  = threadIdx.x;
    const int lane = tid & 31;
    const int wid  = tid >> 5;
    const int wm   = wid & 3;      // M: wm*32
    const int wn   = wid >> 2;     // N: wn*64

    const int n0  = blockIdx.x * 256;
    const int bt0 = blockIdx.y * 2;
    const int b   = bt0 >> 8;

    // ---- A fill mapping: 128 rows x 4 chunks of 8 halves; 512 threads, 1 slot each
    const int ar = tid >> 2;             // 0..127
    const int kc = (tid & 3) << 3;       // 0,8,16,24
    const int tl = ar >> 6;
    const int uu = ar & 63;
    const float* encp  = g_enc  + (size_t)(bt0 + tl) * H_DIM + kc;
    const float* predp = g_pred + ((size_t)b * U_SZ + uu) * H_DIM + kc;
    const uint32_t a_sts_hi = sb + OFF_AHI + (uint32_t)(ar * ROWB + kc * 2);
    const uint32_t a_sts_lo = sb + OFF_ALO + (uint32_t)(ar * ROWB + kc * 2);

    // ---- ldmatrix addressing
    const int arow  = (lane & 7) | (((lane >> 3) & 1) << 3);
    const int akoff = (lane >> 4) << 3;
    const int brow  = lane & 7;
    const int bkoff = ((lane >> 3) & 1) << 3;

    uint32_t aH[2], aL[2];
    #pragma unroll
    for (int mt = 0; mt < 2; mt++) {
        uint32_t off = (uint32_t)(((wm * 32 + mt * 16 + arow) * STRH + akoff) * 2);
        aH[mt] = sb + OFF_AHI + off;
        aL[mt] = sb + OFF_ALO + off;
    }
    const uint32_t bOff = (uint32_t)(((wn * 64 + brow) * STRH + bkoff) * 2);

    float acc[2][8][4];
    #pragma unroll
    for (int mt = 0; mt < 2; mt++)
        #pragma unroll
        for (int nt = 0; nt < 8; nt++)
            #pragma unroll
            for (int i = 0; i < 4; i++) acc[mt][nt][i] = 0.0f;

    // ---- prologue: issue B(0), prefetch A(0)
    {
        #pragma unroll
        for (int i = 0; i < 4; i++) {
            int s   = tid + 512 * i;
            int m   = s >> 10;
            int rs  = s & 1023;
            int row = rs >> 2;
            int chk = rs & 3;
            const __nv_bfloat16* src =
                (m ? g_Wlo : g_Whi) + (size_t)(n0 + row) * H_DIM + chk * 8;
            cp16(sb + OFF_B0 + (uint32_t)(m * B_ONE + row * ROWB + chk * 16), src);
        }
        CP_COMMIT();
    }
    float4 pe0 = *reinterpret_cast<const float4*>(encp);
    float4 pe1 = *reinterpret_cast<const float4*>(encp + 4);
    float4 pp0 = *reinterpret_cast<const float4*>(predp);
    float4 pp1 = *reinterpret_cast<const float4*>(predp + 4);

    #pragma unroll 1
    for (int ch = 0; ch < H_DIM / BK; ch++) {
        CP_WAIT0();

        // ---- A store: relu(enc+pred), bf16 hi/lo split
        {
            float v[8];
            v[0] = pe0.x + pp0.x; v[1] = pe0.y + pp0.y;
            v[2] = pe0.z + pp0.z; v[3] = pe0.w + pp0.w;
            v[4] = pe1.x + pp1.x; v[5] = pe1.y + pp1.y;
            v[6] = pe1.z + pp1.z; v[7] = pe1.w + pp1.w;
            unsigned short hs[8], ls[8];
            #pragma unroll
            for (int i = 0; i < 8; i++) {
                float r = fmaxf(v[i], 0.0f);
                __nv_bfloat16 h = __float2bfloat16_rn(r);
                __nv_bfloat16 l = __float2bfloat16_rn(r - __bfloat162float(h));
                hs[i] = *reinterpret_cast<unsigned short*>(&h);
                ls[i] = *reinterpret_cast<unsigned short*>(&l);
            }
            *reinterpret_cast<uint4*>(smem + (a_sts_hi - sb)) = *reinterpret_cast<uint4*>(hs);
            *reinterpret_cast<uint4*>(smem + (a_sts_lo - sb)) = *reinterpret_cast<uint4*>(ls);
        }
        __syncthreads();

        const uint32_t bbase = sb + OFF_B0 + (uint32_t)((ch & 1) * 2 * B_ONE);

        if (ch < H_DIM / BK - 1) {
            const int k0n = (ch + 1) * BK;
            const uint32_t nbuf = sb + OFF_B0 + (uint32_t)(((ch + 1) & 1) * 2 * B_ONE);
            #pragma unroll
            for (int i = 0; i < 4; i++) {
                int s   = tid + 512 * i;
                int m   = s >> 10;
                int rs  = s & 1023;
                int row = rs >> 2;
                int chk = rs & 3;
                const __nv_bfloat16* src =
                    (m ? g_Wlo : g_Whi) + (size_t)(n0 + row) * H_DIM + k0n + chk * 8;
                cp16(nbuf + (uint32_t)(m * B_ONE + row * ROWB + chk * 16), src);
            }
            CP_COMMIT();
            pe0 = *reinterpret_cast<const float4*>(encp + k0n);
            pe1 = *reinterpret_cast<const float4*>(encp + k0n + 4);
            pp0 = *reinterpret_cast<const float4*>(predp + k0n);
            pp1 = *reinterpret_cast<const float4*>(predp + k0n + 4);
        }

        // ---- MMA: 2 k16 steps x (2 mt x 8 nt x 3 passes)
        #pragma unroll
        for (int ks = 0; ks < 2; ks++) {
            const uint32_t kadd = (uint32_t)(ks * 32);
            uint32_t afh[2][4], afl[2][4];
            #pragma unroll
            for (int mt = 0; mt < 2; mt++) {
                ldmx4(afh[mt], aH[mt] + kadd);
                ldmx4(afl[mt], aL[mt] + kadd);
            }
            #pragma unroll
            for (int nt = 0; nt < 8; nt++) {
                uint32_t bh[2], bl[2];
                const uint32_t ba = bbase + bOff + (uint32_t)(nt * 8 * ROWB) + kadd;
                ldmx2(bh, ba);
                ldmx2(bl, ba + B_ONE);
                #pragma unroll
                for (int mt = 0; mt < 2; mt++) {
                    mma16816(acc[mt][nt], afh[mt], bh);
                    mma16816(acc[mt][nt], afh[mt], bl);
                    mma16816(acc[mt][nt], afl[mt], bh);
                }
            }
        }
        __syncthreads();
    }

    // ---- epilogue: bias + store. Output row = bt0*64 + local_m (contiguous).
    #pragma unroll
    for (int mt = 0; mt < 2; mt++) {
        const int ml = wm * 32 + mt * 16 + (lane >> 2);
        float* orow = out + ((size_t)bt0 * U_SZ + ml) * V_DIM;
        #pragma unroll
        for (int nt = 0; nt < 8; nt++) {
            const int ncol = n0 + wn * 64 + nt * 8 + ((lane & 3) << 1);
            float2 bv = *reinterpret_cast<const float2*>(bout + ncol);
            float2 o0, o1;
            o0.x = acc[mt][nt][0] + bv.x;
            o0.y = acc[mt][nt][1] + bv.y;
            o1.x = acc[mt][nt][2] + bv.x;
            o1.y = acc[mt][nt][3] + bv.y;
            *reinterpret_cast<float2*>(orow + ncol) = o0;
            *reinterpret_cast<float2*>(orow + (size_t)8 * V_DIM + ncol) = o1;
        }
    }
}

// ---------------------------------------------------------------------------
// kernel_launch
// Inputs: 0 enc(4,256,512) 1 pred(4,64,640) 2 W_enc(512,512) 3 b_enc(512)
//         4 W_pred(640,512) 5 b_pred(512) 6 W_out(512,1024) 7 b_out(1024)
// Output: (4,256,64,1024) f32
// ---------------------------------------------------------------------------
extern "C" void kernel_launch(void* const* d_in, const int* in_sizes, int n_in,
                              void* d_out, int out_size)
{
    const float* enc_in  = (const float*)d_in[0];
    const float* pred_in = (const float*)d_in[1];
    const float* W_enc   = (const float*)d_in[2];
    const float* b_enc   = (const float*)d_in[3];
    const float* W_pred  = (const float*)d_in[4];
    const float* b_pred  = (const float*)d_in[5];
    const float* W_out   = (const float*)d_in[6];
    const float* b_out   = (const float*)d_in[7];
    float* out = (float*)d_out;

    cudaFuncSetAttribute(joint_mma_kernel,
                         cudaFuncAttributeMaxDynamicSharedMemorySize, JSMEM);

    // Stage 1: projections into device scratch (fp32)
    proj_kernel<<<dim3(H_DIM / 64, (B_SZ * T_SZ) / 64), 256>>>(
        enc_in, W_enc, b_enc, B_SZ * T_SZ, E_DIM, /*which=*/0);
    proj_kernel<<<dim3(H_DIM / 64, (B_SZ * U_SZ) / 64), 256>>>(
        pred_in, W_pred, b_pred, B_SZ * U_SZ, P_DIM, /*which=*/1);

    // W_out transpose + bf16 split
    split_w_kernel<<<dim3(V_DIM / 32, H_DIM / 32), dim3(32, 8)>>>(W_out);

    // Stage 2: joint GEMM (tensor-core, 3-pass bf16 split)
    joint_mma_kernel<<<dim3(V_DIM / 256, (B_SZ * T_SZ) / 2), 512, JSMEM>>>(b_out, out);
}